// round 16
// baseline (speedup 1.0000x reference)
#include <cuda_runtime.h>
#include <cuda_fp16.h>
#include <cstdint>

// ============================================================
// Scratch (no allocs allowed)
// ============================================================
#define N_MAX 50048
__device__ float g_send_agg[N_MAX * 32];
__device__ float g_recv_agg[N_MAX * 32];
__device__ float g_e2g[64 * 32];
__device__ float g_n2g[64 * 32];
// precomputed partial-product tables (fp32)
__device__ float g_NArecv[N_MAX * 128];   // node_attr @ eW1[0:32]
__device__ float g_NAsend[N_MAX * 128];   // node_attr @ eW1[32:64]
__device__ float g_GcE[64 * 128];         // global @ eW1[96:128] + eb1
__device__ float g_Gc2[64 * 128];         // global @ nW1[32:64]  + nb1
// fp16 weight images, [n][k] packed
__device__ __half g_w1e[128 * 32];        // eW1[64:96]^T   (edge block)
__device__ __half g_w1n[128 * 96];        // nW1 rows {0:32,64:96,96:128}^T
__device__ __half g_w2e[32 * 128];
__device__ __half g_w2n[32 * 128];

__device__ __forceinline__ void red_add_v4(float* p, float a, float b, float c, float d) {
    asm volatile("red.global.add.v4.f32 [%0], {%1, %2, %3, %4};"
                 :: "l"(p), "f"(a), "f"(b), "f"(c), "f"(d) : "memory");
}
__device__ __forceinline__ void mma_f16(float* d, const uint32_t* a, const uint32_t* b) {
    asm volatile(
        "mma.sync.aligned.m16n8k16.row.col.f32.f16.f16.f32 "
        "{%0,%1,%2,%3}, {%4,%5,%6,%7}, {%8,%9}, {%0,%1,%2,%3};"
        : "+f"(d[0]), "+f"(d[1]), "+f"(d[2]), "+f"(d[3])
        : "r"(a[0]), "r"(a[1]), "r"(a[2]), "r"(a[3]), "r"(b[0]), "r"(b[1]));
}
__device__ __forceinline__ uint32_t smem_u32(const void* p) {
    uint32_t a;
    asm("{ .reg .u64 t; cvta.to.shared.u64 t, %1; cvt.u32.u64 %0, t; }" : "=r"(a) : "l"(p));
    return a;
}
#define LDSM_X4(r0, r1, r2, r3, addr) \
    asm volatile("ldmatrix.sync.aligned.m8n8.x4.shared.b16 {%0,%1,%2,%3}, [%4];" \
                 : "=r"(r0), "=r"(r1), "=r"(r2), "=r"(r3) : "r"(addr))

__device__ __forceinline__ uint32_t h2u(float x, float y) {
    __half2 h = __floats2half2_rn(x, y);
    return *reinterpret_cast<uint32_t*>(&h);
}

// ============================================================
// SMEM layout (BYTE offsets)
// P: fp32 partial H, stride 132 floats (528B)
// X: fp16, stride 272B (272 mod 128 = 16 -> conflict-free ldmatrix)
// ============================================================
#define PSTR 132
#define XSTRB 272
#define OFF_P    0                       // 128 x 528
#define OFF_X    67584                   // 128 x 272
#define OFF_W1   102400                  // 128 x 272
#define OFF_W2   137216                  // 32 x 272
#define OFF_Y    145920                  // 128 x 33 f32
#define YSTR 33
#define OFF_B2   162816
#define OFF_GAM  162944
#define OFF_BET  163072
#define OFF_IDXA 163200                  // 128 int
#define OFF_IDXB 163712
#define OFF_IDXC 164224
#define OFF_PS   164736                  // 256 f
#define OFF_PS2  165760
#define SMEM_BYTES 166784

#define GRID_P 148

// ============================================================
// prep_w: weight images + global partial tables
// ============================================================
__global__ void prep_w(const float* eW1, const float* eb1,
                       const float* nW1, const float* nb1,
                       const float* eW2, const float* nW2,
                       const float* global_attr)
{
    int tid = blockIdx.x * blockDim.x + threadIdx.x;
    int nth = gridDim.x * blockDim.x;
    // edge W1c image: [n][k<32] <- eW1[64+k][n]
    for (int i = tid; i < 128 * 32; i += nth) {
        int n = i >> 5, k = i & 31;
        g_w1e[n * 32 + k] = __float2half_rn(eW1[(64 + k) * 128 + n]);
    }
    // node W1 image: [n][k<96] <- nW1 rows {k, 64+(k-32), 96+(k-64)}
    for (int i = tid; i < 128 * 96; i += nth) {
        int n = i / 96, k = i % 96;
        int src = (k < 32) ? k : (k < 64 ? 64 + (k - 32) : 96 + (k - 64));
        g_w1n[n * 96 + k] = __float2half_rn(nW1[src * 128 + n]);
    }
    // W2 images: [n][k<128]
    for (int i = tid; i < 32 * 128; i += nth) {
        int n = i >> 7, k = i & 127;
        g_w2e[n * 128 + k] = __float2half_rn(eW2[k * 32 + n]);
        g_w2n[n * 128 + k] = __float2half_rn(nW2[k * 32 + n]);
    }
    // GcE / Gc2 (fp32)
    for (int i = tid; i < 64 * 128; i += nth) {
        int g = i >> 7, c = i & 127;
        float s1 = eb1[c], s2 = nb1[c];
        for (int j = 0; j < 32; j++) {
            float gv = global_attr[g * 32 + j];
            s1 = fmaf(gv, eW1[(96 + j) * 128 + c], s1);
            s2 = fmaf(gv, nW1[(32 + j) * 128 + c], s2);
        }
        g_GcE[i] = s1;
        g_Gc2[i] = s2;
    }
}

// ============================================================
// prep_na: NArecv/NAsend tables (fp32), persistent blocks
// ============================================================
__global__ __launch_bounds__(256)
void prep_na(const float* __restrict__ node_attr, const float* __restrict__ eW1, int N)
{
    __shared__ float Ws[2][32 * 128];    // recv rows 0:32, send rows 32:64
    __shared__ float nr[32];
    const int tid = threadIdx.x;
    for (int i = tid; i < 32 * 128; i += 256) {
        Ws[0][i] = eW1[i];
        Ws[1][i] = eW1[32 * 128 + i];
    }
    __syncthreads();
    const int tb = tid >> 7, c = tid & 127;
    for (int n = blockIdx.x; n < N; n += gridDim.x) {
        if (tid < 32) nr[tid] = node_attr[n * 32 + tid];
        __syncthreads();
        float acc = 0.f;
#pragma unroll 8
        for (int j = 0; j < 32; j++)
            acc = fmaf(nr[j], Ws[tb][j * 128 + c], acc);
        if (tb == 0) g_NArecv[(size_t)n * 128 + c] = acc;
        else         g_NAsend[(size_t)n * 128 + c] = acc;
        __syncthreads();
    }
}

// ============================================================
// Persistent fused MLP kernel.  MODE 0 = edge (K1=32), 1 = node (K1=96).
// 256 threads = 8 warps.  GEMM1 tiling: warp w -> rows 32*(w>>1), cols 64*(w&1).
// acc initialized from fp32 partial P (precomputed contributions).
// ============================================================
template <int MODE>
__global__ __launch_bounds__(256, 1)
void mlp_kernel(const float* __restrict__ src_main,
                const float* __restrict__ global_attr,
                const int*   __restrict__ edge_index,
                const int*   __restrict__ batch,
                const __half* __restrict__ w1img, const __half* __restrict__ w2img,
                const float* __restrict__ b2g,
                const float* __restrict__ gamg, const float* __restrict__ betg,
                float* __restrict__ out, int count, int E)
{
    extern __shared__ __align__(16) char smem[];
    float* Pf   = (float*)(smem + OFF_P);
    float* Ys   = (float*)(smem + OFF_Y);
    float* b2s  = (float*)(smem + OFF_B2);
    float* gams = (float*)(smem + OFF_GAM);
    float* bets = (float*)(smem + OFF_BET);
    int* idxA = (int*)(smem + OFF_IDXA);
    int* idxB = (int*)(smem + OFF_IDXB);
    int* idxC = (int*)(smem + OFF_IDXC);
    float* ps  = (float*)(smem + OFF_PS);
    float* ps2 = (float*)(smem + OFF_PS2);

    const int tid  = threadIdx.x;
    const int wid  = tid >> 5;
    const int lane = tid & 31;
    const int lt   = lane & 3;
    const int lg   = lane >> 2;

    // ldmatrix lane offsets (fp16 m16n8k16)
    const int aRow = lane & 15;
    const int aKb  = (lane >> 4) << 4;
    const int bN   = ((lane >> 4) << 3) | (lane & 7);
    const int bKb  = ((lane >> 3) & 1) << 4;

    const uint32_t xs_u = smem_u32(smem + OFF_X);
    const uint32_t w1_u = smem_u32(smem + OFF_W1);
    const uint32_t w2_u = smem_u32(smem + OFF_W2);

    const int KP  = MODE ? 96 : 32;      // packed K extent of W1 image
    const int KS1 = MODE ? 6 : 2;        // GEMM1 k-steps

    // ---- one-time: stage weight images (restride -> 272B rows) ----
    {
        const uint4* s1 = (const uint4*)w1img;          // 128 * KP/8 uint4
        const int n1 = 128 * (KP / 8);
        const int cpr = KP / 8;                          // 16B chunks per row
        for (int i = tid; i < n1; i += 256) {
            int n = i / cpr, c = i % cpr;
            *(uint4*)(smem + OFF_W1 + n * XSTRB + c * 16) = s1[i];
        }
        const uint4* s2 = (const uint4*)w2img;          // 32 rows x 16 chunks
        for (int i = tid; i < 512; i += 256) {
            int n = i >> 4, c = i & 15;
            *(uint4*)(smem + OFF_W2 + n * XSTRB + c * 16) = s2[i];
        }
    }
    if (tid < 32) {
        b2s[tid]  = b2g[tid];
        gams[tid] = gamg[tid];
        bets[tid] = betg[tid];
    }
    __syncthreads();

    const int ntiles = (count + 127) >> 7;
    const int step   = gridDim.x;

    for (int t = blockIdx.x; t < ntiles; t += step) {
        const int t0 = t << 7;

        // ---- indices ----
        if (tid < 128) {
            int g = t0 + tid;
            if (MODE == 0) {
                int r = 0, c = 0;
                if (g < count) { r = edge_index[g]; c = edge_index[E + g]; }
                idxA[tid] = r; idxB[tid] = c; idxC[tid] = batch[r];
            } else {
                idxA[tid] = (g < count) ? batch[g] : 0;
            }
        }
        __syncthreads();

        // ---- gather P (fp32 partial H) ----
        for (int i = tid; i < 4096; i += 256) {
            int e = i >> 5, q = i & 31;
            float4 s;
            if (MODE == 0) {
                float4 a = ((const float4*)(g_NArecv + (size_t)idxB[e] * 128))[q];
                float4 b = ((const float4*)(g_NAsend + (size_t)idxA[e] * 128))[q];
                float4 c = ((const float4*)(g_GcE + idxC[e] * 128))[q];
                s.x = a.x + b.x + c.x; s.y = a.y + b.y + c.y;
                s.z = a.z + b.z + c.z; s.w = a.w + b.w + c.w;
            } else {
                s = ((const float4*)(g_Gc2 + idxA[e] * 128))[q];
            }
            *(float4*)(Pf + e * PSTR + 4 * q) = s;
        }

        // ---- gather X (fp16) ----
        if (MODE == 0) {
            // edge_attr only, K=32
            for (int i = tid; i < 512; i += 256) {
                int e = i >> 2, c = i & 3;
                int g = t0 + e;
                float4 u = make_float4(0.f, 0.f, 0.f, 0.f), v = u;
                if (g < count) {
                    const float4* src = (const float4*)(src_main + (size_t)g * 32);
                    u = src[2 * c]; v = src[2 * c + 1];
                }
                uint4 w;
                w.x = h2u(u.x, u.y); w.y = h2u(u.z, u.w);
                w.z = h2u(v.x, v.y); w.w = h2u(v.z, v.w);
                *(uint4*)(smem + OFF_X + e * XSTRB + c * 16) = w;
            }
        } else {
            // [node, recv_agg, send_agg], K=96
            for (int i = tid; i < 1024; i += 256) {
                int e = i >> 3, q = i & 7;
                int g = t0 + e;
                float4 z = make_float4(0.f, 0.f, 0.f, 0.f);
                float4 v0 = z, v1 = z, v2 = z;
                if (g < count) {
                    v0 = *(const float4*)(src_main + (size_t)g * 32 + q * 4);
                    v1 = *(const float4*)(g_recv_agg + (size_t)g * 32 + q * 4);
                    v2 = *(const float4*)(g_send_agg + (size_t)g * 32 + q * 4);
                }
                char* row = smem + OFF_X + e * XSTRB + q * 8;
                *(uint2*)(row)       = make_uint2(h2u(v0.x, v0.y), h2u(v0.z, v0.w));
                *(uint2*)(row + 64)  = make_uint2(h2u(v1.x, v1.y), h2u(v1.z, v1.w));
                *(uint2*)(row + 128) = make_uint2(h2u(v2.x, v2.y), h2u(v2.z, v2.w));
            }
        }
        __syncthreads();

        // ================= GEMM1: H = relu(P + X @ W1c) =================
        {
            const int rbase = 32 * (wid >> 1);
            const int nbase = 64 * (wid & 1);
            const uint32_t aBase = xs_u + (uint32_t)((rbase + aRow) * XSTRB + aKb);
            const uint32_t aBase1 = aBase + 16u * XSTRB;
            const uint32_t bBase = w1_u + (uint32_t)((nbase + bN) * XSTRB + bKb);

            float acc[2][8][4];
#pragma unroll
            for (int mb = 0; mb < 2; mb++)
#pragma unroll
                for (int nb = 0; nb < 8; nb++) {
                    const int r0 = rbase + 16 * mb + lg;
                    const int c0 = nbase + 8 * nb + 2 * lt;
                    *(float2*)&acc[mb][nb][0] = *(float2*)&Pf[r0 * PSTR + c0];
                    *(float2*)&acc[mb][nb][2] = *(float2*)&Pf[(r0 + 8) * PSTR + c0];
                }

#pragma unroll
            for (int s = 0; s < KS1; s++) {
                const uint32_t kb = 32u * s;
                uint32_t a[2][4];
                LDSM_X4(a[0][0], a[0][1], a[0][2], a[0][3], aBase + kb);
                LDSM_X4(a[1][0], a[1][1], a[1][2], a[1][3], aBase1 + kb);
                uint32_t b[8][2];
#pragma unroll
                for (int p = 0; p < 4; p++) {
                    LDSM_X4(b[2 * p][0], b[2 * p][1], b[2 * p + 1][0], b[2 * p + 1][1],
                            bBase + (uint32_t)(16 * p * XSTRB) + kb);
                }
#pragma unroll
                for (int mb = 0; mb < 2; mb++)
#pragma unroll
                    for (int nb = 0; nb < 8; nb++)
                        mma_f16(acc[mb][nb], a[mb], b[nb]);
            }
            __syncthreads();   // X reads done before H overwrites X

            // epilogue1: relu -> fp16 -> X buffer (H[m][l]); bias already in P
#pragma unroll
            for (int nb = 0; nb < 8; nb++) {
                const int c0 = nbase + 8 * nb + 2 * lt;
#pragma unroll
                for (int mb = 0; mb < 2; mb++) {
                    const int r0 = rbase + 16 * mb + lg;
                    uint32_t h01 = h2u(fmaxf(acc[mb][nb][0], 0.f),
                                       fmaxf(acc[mb][nb][1], 0.f));
                    uint32_t h23 = h2u(fmaxf(acc[mb][nb][2], 0.f),
                                       fmaxf(acc[mb][nb][3], 0.f));
                    *(uint32_t*)(smem + OFF_X + r0 * XSTRB + c0 * 2)       = h01;
                    *(uint32_t*)(smem + OFF_X + (r0 + 8) * XSTRB + c0 * 2) = h23;
                }
            }
        }
        __syncthreads();

        // ================= GEMM2: Y = relu(H @ W2 + b2) =================
        {
            const int rbase = 32 * (wid >> 1);
            const int nbase = 16 * (wid & 1);
            const uint32_t aBase = xs_u + (uint32_t)((rbase + aRow) * XSTRB + aKb);
            const uint32_t aBase1 = aBase + 16u * XSTRB;
            const uint32_t bBase  = w2_u + (uint32_t)((nbase + bN) * XSTRB + bKb);

            float acc[2][2][4];
#pragma unroll
            for (int mb = 0; mb < 2; mb++)
#pragma unroll
                for (int nb = 0; nb < 2; nb++)
#pragma unroll
                    for (int f = 0; f < 4; f++) acc[mb][nb][f] = 0.f;

#pragma unroll
            for (int s = 0; s < 8; s++) {
                const uint32_t kb = 32u * s;
                uint32_t a[2][4];
                LDSM_X4(a[0][0], a[0][1], a[0][2], a[0][3], aBase + kb);
                LDSM_X4(a[1][0], a[1][1], a[1][2], a[1][3], aBase1 + kb);
                uint32_t b[2][2];
                LDSM_X4(b[0][0], b[0][1], b[1][0], b[1][1], bBase + kb);
#pragma unroll
                for (int mb = 0; mb < 2; mb++)
#pragma unroll
                    for (int nb = 0; nb < 2; nb++)
                        mma_f16(acc[mb][nb], a[mb], b[nb]);
            }

#pragma unroll
            for (int nb = 0; nb < 2; nb++) {
                const int c0 = nbase + 8 * nb + 2 * lt;
                const float bb0 = b2s[c0], bb1 = b2s[c0 + 1];
#pragma unroll
                for (int mb = 0; mb < 2; mb++) {
                    const int r0 = rbase + 16 * mb + lg;
                    Ys[r0 * YSTR + c0]           = fmaxf(acc[mb][nb][0] + bb0, 0.f);
                    Ys[r0 * YSTR + c0 + 1]       = fmaxf(acc[mb][nb][1] + bb1, 0.f);
                    Ys[(r0 + 8) * YSTR + c0]     = fmaxf(acc[mb][nb][2] + bb0, 0.f);
                    Ys[(r0 + 8) * YSTR + c0 + 1] = fmaxf(acc[mb][nb][3] + bb1, 0.f);
                }
            }
        }
        __syncthreads();

        // ========= LN (split 16/16 across thread pairs) + store + reds =========
        float yv[16];
        {
            const int row = tid & 127, half = tid >> 7;
            const float* yb = Ys + row * YSTR + half * 16;
            float s = 0.f, s2 = 0.f;
#pragma unroll
            for (int j = 0; j < 16; j++) {
                float v = yb[j];
                yv[j] = v;
                s += v;
                s2 = fmaf(v, v, s2);
            }
            ps[tid] = s;
            ps2[tid] = s2;
        }
        __syncthreads();
        {
            const int row = tid & 127, half = tid >> 7;
            const int g = t0 + row;
            if (g < count) {
                float s  = ps[tid] + ps[tid ^ 128];
                float s2 = ps2[tid] + ps2[tid ^ 128];
                float mu = s * (1.f / 32.f);
                float rs = rsqrtf(fmaxf(s2 * (1.f / 32.f) - mu * mu, 0.f) + 1e-5f);
                const int cb = half * 16;
#pragma unroll
                for (int j = 0; j < 16; j++)
                    yv[j] = (yv[j] - mu) * rs * gams[cb + j] + bets[cb + j];

                float4* op = (float4*)(out + (size_t)g * 32 + cb);
#pragma unroll
                for (int j = 0; j < 4; j++)
                    op[j] = make_float4(yv[4 * j], yv[4 * j + 1], yv[4 * j + 2], yv[4 * j + 3]);

                if (MODE == 0) {
                    float* psend = g_send_agg + (size_t)idxA[row] * 32 + cb;
                    float* precv = g_recv_agg + (size_t)idxB[row] * 32 + cb;
                    float* pglob = g_e2g + (size_t)idxC[row] * 32 + cb;
#pragma unroll
                    for (int j = 0; j < 4; j++) {
                        red_add_v4(psend + 4 * j, yv[4 * j], yv[4 * j + 1], yv[4 * j + 2], yv[4 * j + 3]);
                        red_add_v4(precv + 4 * j, yv[4 * j], yv[4 * j + 1], yv[4 * j + 2], yv[4 * j + 3]);
                        red_add_v4(pglob + 4 * j, yv[4 * j], yv[4 * j + 1], yv[4 * j + 2], yv[4 * j + 3]);
                    }
                } else {
                    float* pglob = g_n2g + (size_t)idxA[row] * 32 + cb;
#pragma unroll
                    for (int j = 0; j < 4; j++)
                        red_add_v4(pglob + 4 * j, yv[4 * j], yv[4 * j + 1], yv[4 * j + 2], yv[4 * j + 3]);
                }
            }
        }
        __syncthreads();   // protect idx/P/X/Ys for next tile
    }
}

// ============================================================
// Global model (tiny)
// ============================================================
__global__ __launch_bounds__(128)
void global_kernel(const float* __restrict__ global_attr,
                   const float* __restrict__ W1, const float* __restrict__ b1,
                   const float* __restrict__ W2, const float* __restrict__ b2,
                   float* __restrict__ out_glob)
{
    __shared__ float gin[96];
    __shared__ float hs[128];
    const int g = blockIdx.x, tid = threadIdx.x;
    if (tid < 32) {
        gin[tid]      = g_n2g[g * 32 + tid];
        gin[32 + tid] = g_e2g[g * 32 + tid];
        gin[64 + tid] = global_attr[g * 32 + tid];
    }
    __syncthreads();
    float acc = b1[tid];
#pragma unroll 8
    for (int k = 0; k < 96; k++)
        acc = fmaf(gin[k], W1[k * 128 + tid], acc);
    hs[tid] = fmaxf(acc, 0.f);
    __syncthreads();
    if (tid < 32) {
        float a2 = b2[tid];
#pragma unroll 8
        for (int l = 0; l < 128; l++)
            a2 = fmaf(hs[l], W2[l * 32 + tid], a2);
        out_glob[g * 32 + tid] = fmaxf(a2, 0.f);
    }
}

// ============================================================
// launch
// ============================================================
extern "C" void kernel_launch(void* const* d_in, const int* in_sizes, int n_in,
                              void* d_out, int out_size)
{
    const float* edge_attr   = (const float*)d_in[0];
    const float* node_attr   = (const float*)d_in[1];
    const float* global_attr = (const float*)d_in[2];
    const int*   edge_index  = (const int*)d_in[3];
    const int*   batch       = (const int*)d_in[4];
    const float* eW1 = (const float*)d_in[5];
    const float* eb1 = (const float*)d_in[6];
    const float* eW2 = (const float*)d_in[7];
    const float* eb2 = (const float*)d_in[8];
    const float* eg  = (const float*)d_in[9];
    const float* eB  = (const float*)d_in[10];
    const float* nW1 = (const float*)d_in[11];
    const float* nb1 = (const float*)d_in[12];
    const float* nW2 = (const float*)d_in[13];
    const float* nb2 = (const float*)d_in[14];
    const float* ng  = (const float*)d_in[15];
    const float* nB  = (const float*)d_in[16];
    const float* gW1 = (const float*)d_in[17];
    const float* gb1 = (const float*)d_in[18];
    const float* gW2 = (const float*)d_in[19];
    const float* gb2 = (const float*)d_in[20];

    const int E = in_sizes[0] / 32;
    const int N = in_sizes[1] / 32;
    const int G = in_sizes[2] / 32;

    float* out      = (float*)d_out;
    float* out_edge = out;
    float* out_node = out + (size_t)E * 32;
    float* out_glob = out + (size_t)(E + N) * 32;

    void* p;
    cudaGetSymbolAddress(&p, g_send_agg);
    cudaMemsetAsync(p, 0, (size_t)N * 32 * sizeof(float));
    cudaGetSymbolAddress(&p, g_recv_agg);
    cudaMemsetAsync(p, 0, (size_t)N * 32 * sizeof(float));
    cudaGetSymbolAddress(&p, g_e2g);
    cudaMemsetAsync(p, 0, (size_t)G * 32 * sizeof(float));
    cudaGetSymbolAddress(&p, g_n2g);
    cudaMemsetAsync(p, 0, (size_t)G * 32 * sizeof(float));

    prep_w<<<16, 256>>>(eW1, eb1, nW1, nb1, eW2, nW2, global_attr);
    prep_na<<<512, 256>>>(node_attr, eW1, N);

    cudaFuncSetAttribute(mlp_kernel<0>, cudaFuncAttributeMaxDynamicSharedMemorySize, SMEM_BYTES);
    cudaFuncSetAttribute(mlp_kernel<1>, cudaFuncAttributeMaxDynamicSharedMemorySize, SMEM_BYTES);

    __half *w1ep, *w1np, *w2ep, *w2np;
    cudaGetSymbolAddress((void**)&w1ep, g_w1e);
    cudaGetSymbolAddress((void**)&w1np, g_w1n);
    cudaGetSymbolAddress((void**)&w2ep, g_w2e);
    cudaGetSymbolAddress((void**)&w2np, g_w2n);

    mlp_kernel<0><<<GRID_P, 256, SMEM_BYTES>>>(
        edge_attr, global_attr, edge_index, batch,
        w1ep, w2ep, eb2, eg, eB, out_edge, E, E);

    mlp_kernel<1><<<GRID_P, 256, SMEM_BYTES>>>(
        node_attr, global_attr, edge_index, batch,
        w1np, w2np, nb2, ng, nB, out_node, N, E);

    global_kernel<<<G, 128>>>(global_attr, gW1, gb1, gW2, gb2, out_glob);
}

// round 17
// speedup vs baseline: 1.3787x; 1.3787x over previous
#include <cuda_runtime.h>
#include <cuda_fp16.h>
#include <cstdint>

// ============================================================
// Scratch (no allocs allowed)
// ============================================================
#define N_MAX 50048
__device__ float g_send_agg[N_MAX * 32];
__device__ float g_recv_agg[N_MAX * 32];
__device__ float g_e2g[64 * 32];
__device__ float g_n2g[64 * 32];
// transposed [n][k], fp16 weight images
__device__ __half g_ew1h[128 * 128];
__device__ __half g_ew2h[32 * 128];
__device__ __half g_nw1h[128 * 128];
__device__ __half g_nw2h[32 * 128];

__device__ __forceinline__ void red_add_v4(float* p, float a, float b, float c, float d) {
    asm volatile("red.global.add.v4.f32 [%0], {%1, %2, %3, %4};"
                 :: "l"(p), "f"(a), "f"(b), "f"(c), "f"(d) : "memory");
}
__device__ __forceinline__ void mma_f16(float* d, const uint32_t* a, const uint32_t* b) {
    asm volatile(
        "mma.sync.aligned.m16n8k16.row.col.f32.f16.f16.f32 "
        "{%0,%1,%2,%3}, {%4,%5,%6,%7}, {%8,%9}, {%0,%1,%2,%3};"
        : "+f"(d[0]), "+f"(d[1]), "+f"(d[2]), "+f"(d[3])
        : "r"(a[0]), "r"(a[1]), "r"(a[2]), "r"(a[3]), "r"(b[0]), "r"(b[1]));
}
__device__ __forceinline__ uint32_t smem_u32(const void* p) {
    uint32_t a;
    asm("{ .reg .u64 t; cvta.to.shared.u64 t, %1; cvt.u32.u64 %0, t; }" : "=r"(a) : "l"(p));
    return a;
}
#define LDSM_X4(r0, r1, r2, r3, addr) \
    asm volatile("ldmatrix.sync.aligned.m8n8.x4.shared.b16 {%0,%1,%2,%3}, [%4];" \
                 : "=r"(r0), "=r"(r1), "=r"(r2), "=r"(r3) : "r"(addr))

__device__ __forceinline__ uint32_t h2u(float x, float y) {
    __half2 h = __floats2half2_rn(x, y);
    return *reinterpret_cast<uint32_t*>(&h);
}

// ============================================================
// SMEM layout (BYTE offsets).
// fp16 rows stride 136 halves = 272 B; 272 mod 128 = 16 ->
// every 8-row ldmatrix phase covers all 32 banks once (conflict-free).
// ============================================================
#define XSTRB 272
#define OFF_X    0                     // 128 x 272B
#define OFF_W1   34816                 // 128 x 272B (W1^T [n][k])
#define OFF_W2   69632                 // 32 x 272B  (W2^T [n][k])
#define OFF_Y    78336                 // 128 x 33 fp32
#define YSTR 33
#define OFF_B1   95232                 // 128 f
#define OFF_B2   95744                 // 32 f
#define OFF_GAM  95872
#define OFF_BET  96000
#define OFF_IDXA 96128                 // 128 int
#define OFF_IDXB 96640
#define OFF_IDXC 97152
#define OFF_PS   97664                 // 512 f
#define OFF_PS2  99712                 // 512 f
#define SMEM_BYTES 101760

#define GRID_P 148
#define THREADS 512

// ============================================================
// Weight prep: W[k][n] -> W^T [n][k], fp16
// ============================================================
__global__ void prep_kernel(const float* eW1, const float* eW2,
                            const float* nW1, const float* nW2)
{
    int tid = blockIdx.x * blockDim.x + threadIdx.x;
    int nth = gridDim.x * blockDim.x;
    for (int i = tid; i < 128 * 128; i += nth) {
        int k = i >> 7, n = i & 127;
        g_ew1h[n * 128 + k] = __float2half_rn(eW1[i]);
        g_nw1h[n * 128 + k] = __float2half_rn(nW1[i]);
    }
    for (int i = tid; i < 128 * 32; i += nth) {
        int k = i >> 5, n = i & 31;
        g_ew2h[n * 128 + k] = __float2half_rn(eW2[i]);
        g_nw2h[n * 128 + k] = __float2half_rn(nW2[i]);
    }
}

// ============================================================
// Persistent fused MLP kernel (fp16, 512 threads = 16 warps).
// MODE 0 = edge model, 1 = node model.
// GEMM1: warp w -> rows 16*(w>>1), cols 64*(w&1); 1 mb x 8 nb, 8 ksteps
// GEMM2: warp w -> rows 16*(w>>1), cols 16*(w&1); 1 mb x 2 nb, 8 ksteps
// ============================================================
template <int MODE>
__global__ __launch_bounds__(THREADS, 1)
void mlp_kernel(const float* __restrict__ src_main,
                const float* __restrict__ node_attr,
                const float* __restrict__ global_attr,
                const int*   __restrict__ edge_index,
                const int*   __restrict__ batch,
                const __half* __restrict__ w1img, const __half* __restrict__ w2img,
                const float* __restrict__ b1g, const float* __restrict__ b2g,
                const float* __restrict__ gamg, const float* __restrict__ betg,
                float* __restrict__ out, int count, int E)
{
    extern __shared__ __align__(16) char smem[];
    float* Ys   = (float*)(smem + OFF_Y);
    float* b1s  = (float*)(smem + OFF_B1);
    float* b2s  = (float*)(smem + OFF_B2);
    float* gams = (float*)(smem + OFF_GAM);
    float* bets = (float*)(smem + OFF_BET);
    int* idxA = (int*)(smem + OFF_IDXA);
    int* idxB = (int*)(smem + OFF_IDXB);
    int* idxC = (int*)(smem + OFF_IDXC);
    float* ps  = (float*)(smem + OFF_PS);
    float* ps2 = (float*)(smem + OFF_PS2);

    const int tid  = threadIdx.x;
    const int wid  = tid >> 5;
    const int lane = tid & 31;
    const int lt   = lane & 3;
    const int lg   = lane >> 2;

    // ldmatrix lane offsets (fp16 m16n8k16)
    const int aRow = lane & 15;
    const int aKb  = (lane >> 4) << 4;
    const int bN   = ((lane >> 4) << 3) | (lane & 7);
    const int bKb  = ((lane >> 3) & 1) << 4;

    const uint32_t xs_u = smem_u32(smem + OFF_X);
    const uint32_t w1_u = smem_u32(smem + OFF_W1);
    const uint32_t w2_u = smem_u32(smem + OFF_W2);

    // ---- one-time: stage weights (restride 128 -> 136 halves) ----
    {
        const uint4* s1 = (const uint4*)w1img;          // 2048 x 16B
        for (int i = tid; i < 2048; i += THREADS) {
            int n = i >> 4, c = i & 15;
            *(uint4*)(smem + OFF_W1 + n * XSTRB + c * 16) = s1[i];
        }
        const uint4* s2 = (const uint4*)w2img;          // 512 x 16B
        for (int i = tid; i < 512; i += THREADS) {
            int n = i >> 4, c = i & 15;
            *(uint4*)(smem + OFF_W2 + n * XSTRB + c * 16) = s2[i];
        }
    }
    if (tid < 128) b1s[tid] = b1g[tid];
    if (tid < 32) {
        b2s[tid]  = b2g[tid];
        gams[tid] = gamg[tid];
        bets[tid] = betg[tid];
    }
    __syncthreads();

    const int ntiles = (count + 127) >> 7;
    const int step   = gridDim.x;

    for (int t = blockIdx.x; t < ntiles; t += step) {
        const int t0 = t << 7;

        // ---- indices ----
        if (tid < 128) {
            int g = t0 + tid;
            if (MODE == 0) {
                int r = 0, c = 0;
                if (g < count) { r = edge_index[g]; c = edge_index[E + g]; }
                idxA[tid] = r; idxB[tid] = c; idxC[tid] = batch[r];
            } else {
                idxA[tid] = (g < count) ? batch[g] : 0;
            }
        }
        __syncthreads();

        // ---- gather X[m][k] -> fp16 SMEM ----
        for (int i = tid; i < 1024; i += THREADS) {
            int e = i >> 3, q = i & 7;
            int g = t0 + e;
            float4 z = make_float4(0.f, 0.f, 0.f, 0.f);
            float4 v0 = z, v1 = z, v2 = z, v3 = z;
            if (g < count) {
                if (MODE == 0) {
                    v0 = *(const float4*)(node_attr + (size_t)idxB[e] * 32 + q * 4);
                    v1 = *(const float4*)(node_attr + (size_t)idxA[e] * 32 + q * 4);
                    v2 = *(const float4*)(src_main + (size_t)g * 32 + q * 4);
                    v3 = *(const float4*)(global_attr + (size_t)idxC[e] * 32 + q * 4);
                } else {
                    v0 = *(const float4*)(src_main + (size_t)g * 32 + q * 4);
                    v1 = *(const float4*)(global_attr + (size_t)idxA[e] * 32 + q * 4);
                    v2 = *(const float4*)(g_recv_agg + (size_t)g * 32 + q * 4);
                    v3 = *(const float4*)(g_send_agg + (size_t)g * 32 + q * 4);
                }
            }
            char* row = smem + OFF_X + e * XSTRB + q * 8;
            *(uint2*)(row)       = make_uint2(h2u(v0.x, v0.y), h2u(v0.z, v0.w));
            *(uint2*)(row + 64)  = make_uint2(h2u(v1.x, v1.y), h2u(v1.z, v1.w));
            *(uint2*)(row + 128) = make_uint2(h2u(v2.x, v2.y), h2u(v2.z, v2.w));
            *(uint2*)(row + 192) = make_uint2(h2u(v3.x, v3.y), h2u(v3.z, v3.w));
        }
        __syncthreads();

        // ================= GEMM1: H = relu(X @ W1 + b1) =================
        {
            const int rbase = 16 * (wid >> 1);
            const int nbase = 64 * (wid & 1);
            const uint32_t aBase = xs_u + (uint32_t)((rbase + aRow) * XSTRB + aKb);
            const uint32_t bBase = w1_u + (uint32_t)((nbase + bN) * XSTRB + bKb);

            float acc[8][4];
#pragma unroll
            for (int nb = 0; nb < 8; nb++)
#pragma unroll
                for (int f = 0; f < 4; f++) acc[nb][f] = 0.f;

#pragma unroll
            for (int s = 0; s < 8; s++) {
                const uint32_t kb = 32u * s;
                uint32_t a[4];
                LDSM_X4(a[0], a[1], a[2], a[3], aBase + kb);
                uint32_t b[8][2];
#pragma unroll
                for (int p = 0; p < 4; p++) {
                    LDSM_X4(b[2 * p][0], b[2 * p][1], b[2 * p + 1][0], b[2 * p + 1][1],
                            bBase + (uint32_t)(16 * p * XSTRB) + kb);
                }
#pragma unroll
                for (int nb = 0; nb < 8; nb++)
                    mma_f16(acc[nb], a, b[nb]);
            }
            __syncthreads();   // all X/W1 reads done before H overwrites X

            // epilogue1: relu(+b1) -> fp16 -> X buffer (H[m][l])
#pragma unroll
            for (int nb = 0; nb < 8; nb++) {
                const int c0 = nbase + 8 * nb + 2 * lt;
                const float bb0 = b1s[c0], bb1 = b1s[c0 + 1];
                const int r0 = rbase + lg;
                uint32_t h01 = h2u(fmaxf(acc[nb][0] + bb0, 0.f),
                                   fmaxf(acc[nb][1] + bb1, 0.f));
                uint32_t h23 = h2u(fmaxf(acc[nb][2] + bb0, 0.f),
                                   fmaxf(acc[nb][3] + bb1, 0.f));
                *(uint32_t*)(smem + OFF_X + r0 * XSTRB + c0 * 2)       = h01;
                *(uint32_t*)(smem + OFF_X + (r0 + 8) * XSTRB + c0 * 2) = h23;
            }
        }
        __syncthreads();

        // ================= GEMM2: Y = relu(H @ W2 + b2) =================
        {
            const int rbase = 16 * (wid >> 1);
            const int nbase = 16 * (wid & 1);
            const uint32_t aBase = xs_u + (uint32_t)((rbase + aRow) * XSTRB + aKb);
            const uint32_t bBase = w2_u + (uint32_t)((nbase + bN) * XSTRB + bKb);

            float acc[2][4];
#pragma unroll
            for (int nb = 0; nb < 2; nb++)
#pragma unroll
                for (int f = 0; f < 4; f++) acc[nb][f] = 0.f;

#pragma unroll
            for (int s = 0; s < 8; s++) {
                const uint32_t kb = 32u * s;
                uint32_t a[4];
                LDSM_X4(a[0], a[1], a[2], a[3], aBase + kb);
                uint32_t b[2][2];
                LDSM_X4(b[0][0], b[0][1], b[1][0], b[1][1], bBase + kb);
#pragma unroll
                for (int nb = 0; nb < 2; nb++)
                    mma_f16(acc[nb], a, b[nb]);
            }

#pragma unroll
            for (int nb = 0; nb < 2; nb++) {
                const int c0 = nbase + 8 * nb + 2 * lt;
                const float bb0 = b2s[c0], bb1 = b2s[c0 + 1];
                const int r0 = rbase + lg;
                Ys[r0 * YSTR + c0]           = fmaxf(acc[nb][0] + bb0, 0.f);
                Ys[r0 * YSTR + c0 + 1]       = fmaxf(acc[nb][1] + bb1, 0.f);
                Ys[(r0 + 8) * YSTR + c0]     = fmaxf(acc[nb][2] + bb0, 0.f);
                Ys[(r0 + 8) * YSTR + c0 + 1] = fmaxf(acc[nb][3] + bb1, 0.f);
            }
        }
        __syncthreads();

        // ========= LN (split 8/8/8/8 across thread quads) + store + reds =========
        float yv[8];
        {
            const int row = tid & 127, qt = tid >> 7;
            const float* yb = Ys + row * YSTR + qt * 8;
            float s = 0.f, s2 = 0.f;
#pragma unroll
            for (int j = 0; j < 8; j++) {
                float v = yb[j];
                yv[j] = v;
                s += v;
                s2 = fmaf(v, v, s2);
            }
            ps[tid] = s;
            ps2[tid] = s2;
        }
        __syncthreads();
        {
            const int row = tid & 127, qt = tid >> 7;
            const int g = t0 + row;
            if (g < count) {
                float s  = ps[row] + ps[row + 128] + ps[row + 256] + ps[row + 384];
                float s2 = ps2[row] + ps2[row + 128] + ps2[row + 256] + ps2[row + 384];
                float mu = s * (1.f / 32.f);
                float rs = rsqrtf(fmaxf(s2 * (1.f / 32.f) - mu * mu, 0.f) + 1e-5f);
                const int cb = qt * 8;
#pragma unroll
                for (int j = 0; j < 8; j++)
                    yv[j] = (yv[j] - mu) * rs * gams[cb + j] + bets[cb + j];

                float4* op = (float4*)(out + (size_t)g * 32 + cb);
                op[0] = make_float4(yv[0], yv[1], yv[2], yv[3]);
                op[1] = make_float4(yv[4], yv[5], yv[6], yv[7]);

                if (MODE == 0) {
                    float* psend = g_send_agg + (size_t)idxA[row] * 32 + cb;
                    float* precv = g_recv_agg + (size_t)idxB[row] * 32 + cb;
                    float* pglob = g_e2g + (size_t)idxC[row] * 32 + cb;
#pragma unroll
                    for (int j = 0; j < 2; j++) {
                        red_add_v4(psend + 4 * j, yv[4 * j], yv[4 * j + 1], yv[4 * j + 2], yv[4 * j + 3]);
                        red_add_v4(precv + 4 * j, yv[4 * j], yv[4 * j + 1], yv[4 * j + 2], yv[4 * j + 3]);
                        red_add_v4(pglob + 4 * j, yv[4 * j], yv[4 * j + 1], yv[4 * j + 2], yv[4 * j + 3]);
                    }
                } else {
                    float* pglob = g_n2g + (size_t)idxA[row] * 32 + cb;
#pragma unroll
                    for (int j = 0; j < 2; j++)
                        red_add_v4(pglob + 4 * j, yv[4 * j], yv[4 * j + 1], yv[4 * j + 2], yv[4 * j + 3]);
                }
            }
        }
        __syncthreads();   // protect idx/X/Ys for next tile
    }
}

// ============================================================
// Global model (tiny)
// ============================================================
__global__ __launch_bounds__(128)
void global_kernel(const float* __restrict__ global_attr,
                   const float* __restrict__ W1, const float* __restrict__ b1,
                   const float* __restrict__ W2, const float* __restrict__ b2,
                   float* __restrict__ out_glob)
{
    __shared__ float gin[96];
    __shared__ float hs[128];
    const int g = blockIdx.x, tid = threadIdx.x;
    if (tid < 32) {
        gin[tid]      = g_n2g[g * 32 + tid];
        gin[32 + tid] = g_e2g[g * 32 + tid];
        gin[64 + tid] = global_attr[g * 32 + tid];
    }
    __syncthreads();
    float acc = b1[tid];
#pragma unroll 8
    for (int k = 0; k < 96; k++)
        acc = fmaf(gin[k], W1[k * 128 + tid], acc);
    hs[tid] = fmaxf(acc, 0.f);
    __syncthreads();
    if (tid < 32) {
        float a2 = b2[tid];
#pragma unroll 8
        for (int l = 0; l < 128; l++)
            a2 = fmaf(hs[l], W2[l * 32 + tid], a2);
        out_glob[g * 32 + tid] = fmaxf(a2, 0.f);
    }
}

// ============================================================
// launch
// ============================================================
extern "C" void kernel_launch(void* const* d_in, const int* in_sizes, int n_in,
                              void* d_out, int out_size)
{
    const float* edge_attr   = (const float*)d_in[0];
    const float* node_attr   = (const float*)d_in[1];
    const float* global_attr = (const float*)d_in[2];
    const int*   edge_index  = (const int*)d_in[3];
    const int*   batch       = (const int*)d_in[4];
    const float* eW1 = (const float*)d_in[5];
    const float* eb1 = (const float*)d_in[6];
    const float* eW2 = (const float*)d_in[7];
    const float* eb2 = (const float*)d_in[8];
    const float* eg  = (const float*)d_in[9];
    const float* eB  = (const float*)d_in[10];
    const float* nW1 = (const float*)d_in[11];
    const float* nb1 = (const float*)d_in[12];
    const float* nW2 = (const float*)d_in[13];
    const float* nb2 = (const float*)d_in[14];
    const float* ng  = (const float*)d_in[15];
    const float* nB  = (const float*)d_in[16];
    const float* gW1 = (const float*)d_in[17];
    const float* gb1 = (const float*)d_in[18];
    const float* gW2 = (const float*)d_in[19];
    const float* gb2 = (const float*)d_in[20];

    const int E = in_sizes[0] / 32;
    const int N = in_sizes[1] / 32;
    const int G = in_sizes[2] / 32;

    float* out      = (float*)d_out;
    float* out_edge = out;
    float* out_node = out + (size_t)E * 32;
    float* out_glob = out + (size_t)(E + N) * 32;

    void* p;
    cudaGetSymbolAddress(&p, g_send_agg);
    cudaMemsetAsync(p, 0, (size_t)N * 32 * sizeof(float));
    cudaGetSymbolAddress(&p, g_recv_agg);
    cudaMemsetAsync(p, 0, (size_t)N * 32 * sizeof(float));
    cudaGetSymbolAddress(&p, g_e2g);
    cudaMemsetAsync(p, 0, (size_t)G * 32 * sizeof(float));
    cudaGetSymbolAddress(&p, g_n2g);
    cudaMemsetAsync(p, 0, (size_t)G * 32 * sizeof(float));

    prep_kernel<<<8, 256>>>(eW1, eW2, nW1, nW2);

    cudaFuncSetAttribute(mlp_kernel<0>, cudaFuncAttributeMaxDynamicSharedMemorySize, SMEM_BYTES);
    cudaFuncSetAttribute(mlp_kernel<1>, cudaFuncAttributeMaxDynamicSharedMemorySize, SMEM_BYTES);

    __half *ew1p, *ew2p, *nw1p, *nw2p;
    cudaGetSymbolAddress((void**)&ew1p, g_ew1h);
    cudaGetSymbolAddress((void**)&ew2p, g_ew2h);
    cudaGetSymbolAddress((void**)&nw1p, g_nw1h);
    cudaGetSymbolAddress((void**)&nw2p, g_nw2h);

    mlp_kernel<0><<<GRID_P, THREADS, SMEM_BYTES>>>(
        edge_attr, node_attr, global_attr, edge_index, batch,
        ew1p, ew2p, eb1, eb2, eg, eB, out_edge, E, E);

    mlp_kernel<1><<<GRID_P, THREADS, SMEM_BYTES>>>(
        node_attr, node_attr, global_attr, edge_index, batch,
        nw1p, nw2p, nb1, nb2, ng, nB, out_node, N, E);

    global_kernel<<<G, 128>>>(global_attr, gW1, gb1, gW2, gb2, out_glob);
}